// round 15
// baseline (speedup 1.0000x reference)
#include <cuda_runtime.h>
#include <cuda_bf16.h>
#include <cuda_fp16.h>
#include <cstdint>

#define BATCH 8
#define SEQ   2048
#define EMB   1024
#define MTOT  (BATCH*SEQ)   // 16384
typedef __nv_bfloat16 bf16;

// ------------------------------ scratch --------------------------------------
#define DA __device__ __align__(256)
DA bf16 g_wqsh[1024*1024], g_wqsl[1024*1024];       // Wq split (no transpose)
DA bf16 g_wksh[1024*1024], g_wksl[1024*1024];       // Wk split
DA bf16 g_mth[1024*1024],  g_mtl[1024*1024];        // (Wq Wk^T)^T split
DA __half g_wvt[1024*1024];                         // Wv^T fp16
DA __half g_wft[1024*1024];                         // Wfc^T fp16
DA bf16 g_hh[(size_t)MTOT*EMB],  g_hl[(size_t)MTOT*EMB];
DA __half g_h16[(size_t)MTOT*EMB];                  // LN out fp16 (reused LN1/LN2)
DA bf16 g_gh[(size_t)MTOT*EMB],  g_gl[(size_t)MTOT*EMB];  // g = h@M split
DA __half g_vt16[(size_t)MTOT*EMB];                 // v^T fp16 [B][EI][S]
DA float g_s[(size_t)BATCH*SEQ*SEQ];
DA __half g_p16[(size_t)BATCH*SEQ*SEQ];             // probs fp16
DA float g_o[(size_t)MTOT*EMB];
DA float g_zero[2048];                              // zero-initialized
DA float g_w1[1024], g_w2[1024];                    // Wq@bk, Wk@bq
DA float g_c1[MTOT], g_c2[MTOT];                    // h@w1, h@w2
DA float g_c3[1];                                   // bq.bk

// ------------------------------ helpers --------------------------------------
__device__ __forceinline__ uint32_t smem_u32(const void* p) {
    uint32_t a;
    asm("{ .reg .u64 t; cvta.to.shared.u64 t, %1; cvt.u32.u64 %0, t; }" : "=r"(a) : "l"(p));
    return a;
}
__device__ __forceinline__ void ldsm4(uint32_t* r, uint32_t addr) {
    asm volatile("ldmatrix.sync.aligned.m8n8.x4.shared.b16 {%0,%1,%2,%3}, [%4];"
        : "=r"(r[0]), "=r"(r[1]), "=r"(r[2]), "=r"(r[3]) : "r"(addr));
}
__device__ __forceinline__ void mma_bf(float* d, const uint32_t* a, uint32_t b0, uint32_t b1) {
    asm volatile("mma.sync.aligned.m16n8k16.row.col.f32.bf16.bf16.f32 "
        "{%0,%1,%2,%3},{%4,%5,%6,%7},{%8,%9},{%0,%1,%2,%3};"
        : "+f"(d[0]), "+f"(d[1]), "+f"(d[2]), "+f"(d[3])
        : "r"(a[0]), "r"(a[1]), "r"(a[2]), "r"(a[3]), "r"(b0), "r"(b1));
}
__device__ __forceinline__ void mma_fp(float* d, const uint32_t* a, uint32_t b0, uint32_t b1) {
    asm volatile("mma.sync.aligned.m16n8k16.row.col.f32.f16.f16.f32 "
        "{%0,%1,%2,%3},{%4,%5,%6,%7},{%8,%9},{%0,%1,%2,%3};"
        : "+f"(d[0]), "+f"(d[1]), "+f"(d[2]), "+f"(d[3])
        : "r"(a[0]), "r"(a[1]), "r"(a[2]), "r"(a[3]), "r"(b0), "r"(b1));
}

static constexpr int PITCH = 80;
static constexpr int ATILE = 128*PITCH;
static constexpr int BTILE = 64*PITCH;
static constexpr int STG3  = 2*ATILE + 2*BTILE;  // 30720
static constexpr int SMB3  = 2*STG3;             // 61440
static constexpr int STG1  = ATILE + BTILE;      // 15360
static constexpr int SMB1  = 2*STG1;             // 30720

// =============================== mm3: bf16 3-term split =======================
// C[128x64 per CTA] = (A0+A1) @ (B0+B1)^T via hi*hi + hi*lo + lo*hi.
// EPI: 0 -> Cf=acc | 2 -> split(acc+bias)->Ch,Cl | 4 -> Cf=acc+r1[row]+r2[col]+c3
template<int EPI>
__global__ void __launch_bounds__(256, 2) mm_hmma(
    const bf16* __restrict__ A0, const bf16* __restrict__ A1,
    const bf16* __restrict__ B0, const bf16* __restrict__ B1,
    const float* __restrict__ bias,
    const float* __restrict__ r1, const float* __restrict__ r2,
    const float* __restrict__ c3p,
    float* __restrict__ Cf, bf16* __restrict__ Ch, bf16* __restrict__ Cl,
    int N, int K, long long sA, long long sB, long long sC)
{
    extern __shared__ char sm[];
    const int tid = threadIdx.x, lane = tid & 31, warp = tid >> 5;
    const long long bz = blockIdx.z;
    const int row0 = blockIdx.y * 128, col0 = blockIdx.x * 64;
    const bf16* srcs[4] = {
        A0 + sA*bz + (long long)row0*K,
        A1 + sA*bz + (long long)row0*K,
        B0 + sB*bz + (long long)col0*K,
        B1 + sB*bz + (long long)col0*K };
    const uint32_t sb = smem_u32(sm);

    auto stage_load = [&](int c, int buf) {
        const int k0 = c * 32;
        const uint32_t db = sb + buf * STG3;
        #pragma unroll
        for (int i = 0; i < 4; ++i) {            // A0,A1
            int idx  = tid + i * 256;
            int tile = idx >> 9;
            int row  = (idx >> 2) & 127;
            int ch   = idx & 3;
            const bf16* s = srcs[tile] + (long long)row * K + k0 + ch * 8;
            uint32_t d = db + tile * ATILE + row * PITCH + ch * 16;
            asm volatile("cp.async.cg.shared.global [%0], [%1], 16;" :: "r"(d), "l"(s));
        }
        #pragma unroll
        for (int i = 0; i < 2; ++i) {            // B0,B1
            int j    = tid + i * 256;
            int tile = j >> 8;
            int row  = (j >> 2) & 63;
            int ch   = j & 3;
            const bf16* s = srcs[2 + tile] + (long long)row * K + k0 + ch * 8;
            uint32_t d = db + 2*ATILE + tile * BTILE + row * PITCH + ch * 16;
            asm volatile("cp.async.cg.shared.global [%0], [%1], 16;" :: "r"(d), "l"(s));
        }
        asm volatile("cp.async.commit_group;" ::: "memory");
    };

    const int wr = (warp & 3) * 32;
    const int wc = (warp >> 2) * 32;
    float acc[2][4][4] = {};

    const int rA = lane & 15;
    const int byA = (lane >> 4) * 16;
    const int rB = (lane & 7) + ((lane >> 3) & 1) * 8;
    const int byB = ((lane >> 4) & 1) * 16;

    const int nch = K >> 5;
    stage_load(0, 0);
    for (int c = 0; c < nch; ++c) {
        const int buf = c & 1;
        if (c + 1 < nch) {
            stage_load(c + 1, buf ^ 1);
            asm volatile("cp.async.wait_group 1;" ::: "memory");
        } else {
            asm volatile("cp.async.wait_group 0;" ::: "memory");
        }
        __syncthreads();
        const uint32_t base = sb + buf * STG3;
        #pragma unroll
        for (int ks = 0; ks < 2; ++ks) {
            const int kb = ks * 32;
            uint32_t ah[2][4], al[2][4], bh[2][4], bl[2][4];
            #pragma unroll
            for (int mi = 0; mi < 2; ++mi) {
                ldsm4(ah[mi], base + (wr + mi*16 + rA) * PITCH + byA + kb);
                ldsm4(al[mi], base + ATILE + (wr + mi*16 + rA) * PITCH + byA + kb);
            }
            #pragma unroll
            for (int ng = 0; ng < 2; ++ng) {
                ldsm4(bh[ng], base + 2*ATILE + (wc + ng*16 + rB) * PITCH + byB + kb);
                ldsm4(bl[ng], base + 2*ATILE + BTILE + (wc + ng*16 + rB) * PITCH + byB + kb);
            }
            #pragma unroll
            for (int mi = 0; mi < 2; ++mi)
                #pragma unroll
                for (int nj = 0; nj < 4; ++nj) {
                    mma_bf(acc[mi][nj], ah[mi], bh[nj>>1][nj&1], bh[nj>>1][(nj&1)+2]);
                    mma_bf(acc[mi][nj], ah[mi], bl[nj>>1][nj&1], bl[nj>>1][(nj&1)+2]);
                    mma_bf(acc[mi][nj], al[mi], bh[nj>>1][nj&1], bh[nj>>1][(nj&1)+2]);
                }
        }
        __syncthreads();
    }

    const int rb = row0 + wr + (lane >> 2);
    const int cb = col0 + wc + (lane & 3) * 2;
    #pragma unroll
    for (int mi = 0; mi < 2; ++mi)
        #pragma unroll
        for (int h = 0; h < 2; ++h) {
            const int r = rb + mi * 16 + h * 8;
            #pragma unroll
            for (int nj = 0; nj < 4; ++nj) {
                const int colg = cb + nj * 8;
                const long long oi = sC * bz + (long long)r * N + colg;
                float v0 = acc[mi][nj][2*h], v1 = acc[mi][nj][2*h + 1];
                if (EPI == 0) {
                    *(float2*)(Cf + oi) = make_float2(v0, v1);
                } else if (EPI == 2) {
                    v0 += bias[colg]; v1 += bias[colg + 1];
                    bf16 h0 = __float2bfloat16(v0), h1 = __float2bfloat16(v1);
                    bf16 l0 = __float2bfloat16(v0 - __bfloat162float(h0));
                    bf16 l1 = __float2bfloat16(v1 - __bfloat162float(h1));
                    *(__nv_bfloat162*)(Ch + oi) = __nv_bfloat162(h0, h1);
                    *(__nv_bfloat162*)(Cl + oi) = __nv_bfloat162(l0, l1);
                } else {  // EPI == 4 (scores with rank-1 bias terms)
                    const float base_add = r1[bz*N + r] + c3p[0];
                    *(float2*)(Cf + oi) = make_float2(
                        v0 + base_add + r2[bz*N + colg],
                        v1 + base_add + r2[bz*N + colg + 1]);
                }
            }
        }
}

// =============================== mm1: fp16 single-term ========================
// EPI: 0 -> Cf=acc | 1 -> Cf=acc+bias | 3 -> Cf=2*(acc+bias+X)
// EPI: 5 -> fp16 TRANSPOSED out: Ct[b][col][row_local] = acc+bias (v-proj fused v^T)
template<int EPI>
__global__ void __launch_bounds__(256, 2) mm_fp16(
    const __half* __restrict__ A, const __half* __restrict__ B,
    const float* __restrict__ bias, const float* __restrict__ X,
    float* __restrict__ Cf, __half* __restrict__ Ct,
    int N, int K, long long sA, long long sB, long long sC)
{
    extern __shared__ char sm[];
    const int tid = threadIdx.x, lane = tid & 31, warp = tid >> 5;
    const long long bz = blockIdx.z;
    const int row0 = blockIdx.y * 128, col0 = blockIdx.x * 64;
    const __half* srcA = A + sA*bz + (long long)row0*K;
    const __half* srcB = B + sB*bz + (long long)col0*K;
    const uint32_t sb = smem_u32(sm);

    auto stage_load = [&](int c, int buf) {
        const int k0 = c * 32;
        const uint32_t db = sb + buf * STG1;
        #pragma unroll
        for (int i = 0; i < 2; ++i) {
            int idx = tid + i * 256;
            int row = (idx >> 2) & 127;
            int ch  = idx & 3;
            const __half* s = srcA + (long long)row * K + k0 + ch * 8;
            uint32_t d = db + row * PITCH + ch * 16;
            asm volatile("cp.async.cg.shared.global [%0], [%1], 16;" :: "r"(d), "l"(s));
        }
        {
            int row = (tid >> 2) & 63;
            int ch  = tid & 3;
            const __half* s = srcB + (long long)row * K + k0 + ch * 8;
            uint32_t d = db + ATILE + row * PITCH + ch * 16;
            asm volatile("cp.async.cg.shared.global [%0], [%1], 16;" :: "r"(d), "l"(s));
        }
        asm volatile("cp.async.commit_group;" ::: "memory");
    };

    const int wr = (warp & 3) * 32;
    const int wc = (warp >> 2) * 32;
    float acc[2][4][4] = {};

    const int rA = lane & 15;
    const int byA = (lane >> 4) * 16;
    const int rB = (lane & 7) + ((lane >> 3) & 1) * 8;
    const int byB = ((lane >> 4) & 1) * 16;

    const int nch = K >> 5;
    stage_load(0, 0);
    for (int c = 0; c < nch; ++c) {
        const int buf = c & 1;
        if (c + 1 < nch) {
            stage_load(c + 1, buf ^ 1);
            asm volatile("cp.async.wait_group 1;" ::: "memory");
        } else {
            asm volatile("cp.async.wait_group 0;" ::: "memory");
        }
        __syncthreads();
        const uint32_t base = sb + buf * STG1;
        #pragma unroll
        for (int ks = 0; ks < 2; ++ks) {
            const int kb = ks * 32;
            uint32_t ah[2][4], bh[2][4];
            #pragma unroll
            for (int mi = 0; mi < 2; ++mi)
                ldsm4(ah[mi], base + (wr + mi*16 + rA) * PITCH + byA + kb);
            #pragma unroll
            for (int ng = 0; ng < 2; ++ng)
                ldsm4(bh[ng], base + ATILE + (wc + ng*16 + rB) * PITCH + byB + kb);
            #pragma unroll
            for (int mi = 0; mi < 2; ++mi)
                #pragma unroll
                for (int nj = 0; nj < 4; ++nj)
                    mma_fp(acc[mi][nj], ah[mi], bh[nj>>1][nj&1], bh[nj>>1][(nj&1)+2]);
        }
        __syncthreads();
    }

    const int rb = row0 + wr + (lane >> 2);
    const int cb = col0 + wc + (lane & 3) * 2;
    __half* st = (__half*)sm;   // EPI==5 staging: [64 cols][pitch 136 halves]
    #pragma unroll
    for (int mi = 0; mi < 2; ++mi)
        #pragma unroll
        for (int h = 0; h < 2; ++h) {
            const int r = rb + mi * 16 + h * 8;
            #pragma unroll
            for (int nj = 0; nj < 4; ++nj) {
                const int colg = cb + nj * 8;
                float v0 = acc[mi][nj][2*h], v1 = acc[mi][nj][2*h + 1];
                if (EPI == 5) {
                    const int lr = r - row0, lc = colg - col0;
                    st[lc * 136 + lr]       = __float2half(v0 + bias[colg]);
                    st[(lc + 1) * 136 + lr] = __float2half(v1 + bias[colg + 1]);
                } else {
                    const long long oi = sC * bz + (long long)r * N + colg;
                    if (EPI == 0) {
                        *(float2*)(Cf + oi) = make_float2(v0, v1);
                    } else if (EPI == 1) {
                        *(float2*)(Cf + oi) = make_float2(v0 + bias[colg], v1 + bias[colg+1]);
                    } else {
                        const float2 xb = *(const float2*)(X + oi);
                        *(float2*)(Cf + oi) = make_float2(2.0f*(v0 + bias[colg]   + xb.x),
                                                          2.0f*(v1 + bias[colg+1] + xb.y));
                    }
                }
            }
        }
    if (EPI == 5) {
        __syncthreads();
        const int b = row0 >> 11;               // 128-row tile lies in one batch
        const int s0 = row0 & 2047;
        #pragma unroll
        for (int i = 0; i < 4; ++i) {
            int ch = tid + i * 256;             // 1024 chunks of 8 halves
            int c = ch >> 4, off = (ch & 15) * 8;
            uint4 val = *(const uint4*)(st + c * 136 + off);
            *(uint4*)(Ct + ((long long)b * EMB + col0 + c) * SEQ + s0 + off) = val;
        }
    }
}

// ------------------------------ reductions -----------------------------------
__device__ __forceinline__ float brSum(float v, float* sh) {
    #pragma unroll
    for (int o = 16; o > 0; o >>= 1) v += __shfl_down_sync(0xffffffffu, v, o);
    int ln = threadIdx.x & 31, w = threadIdx.x >> 5;
    __syncthreads();
    if (ln == 0) sh[w] = v;
    __syncthreads();
    if (w == 0) {
        v = (ln < 8) ? sh[ln] : 0.0f;
        #pragma unroll
        for (int o = 4; o > 0; o >>= 1) v += __shfl_down_sync(0xffffffffu, v, o);
        if (ln == 0) sh[0] = v;
    }
    __syncthreads();
    return sh[0];
}
__device__ __forceinline__ float brMax(float v, float* sh) {
    #pragma unroll
    for (int o = 16; o > 0; o >>= 1) v = fmaxf(v, __shfl_down_sync(0xffffffffu, v, o));
    int ln = threadIdx.x & 31, w = threadIdx.x >> 5;
    __syncthreads();
    if (ln == 0) sh[w] = v;
    __syncthreads();
    if (w == 0) {
        v = (ln < 8) ? sh[ln] : -1e30f;
        #pragma unroll
        for (int o = 4; o > 0; o >>= 1) v = fmaxf(v, __shfl_down_sync(0xffffffffu, v, o));
        if (ln == 0) sh[0] = v;
    }
    __syncthreads();
    return sh[0];
}

// ------------------------------ LN (vectorized, optional fused matvecs) -------
__global__ void __launch_bounds__(256) ln_kernel(
    const float* __restrict__ x, const float* __restrict__ g,
    const float* __restrict__ b, bf16* __restrict__ oh, bf16* __restrict__ ol,
    __half* __restrict__ o16,
    const float* __restrict__ w1, const float* __restrict__ w2,
    float* __restrict__ oc1, float* __restrict__ oc2)
{
    __shared__ float sh[32];
    const long long row = blockIdx.x;
    const int tid = threadIdx.x;
    const float4 t = ((const float4*)(x + row*EMB))[tid];
    float s  = t.x + t.y + t.z + t.w;
    float s2 = t.x*t.x + t.y*t.y + t.z*t.z + t.w*t.w;
    s  = brSum(s,  sh);
    s2 = brSum(s2, sh);
    const float mu  = s * (1.0f/EMB);
    const float inv = rsqrtf(s2*(1.0f/EMB) - mu*mu + 1e-5f);
    const float4 gv = ((const float4*)g)[tid];
    const float4 bv = ((const float4*)b)[tid];
    float y0 = (t.x - mu)*inv*gv.x + bv.x;
    float y1 = (t.y - mu)*inv*gv.y + bv.y;
    float y2 = (t.z - mu)*inv*gv.z + bv.z;
    float y3 = (t.w - mu)*inv*gv.w + bv.w;
    const long long o = row*EMB + tid*4;
    if (oh) {
        bf16 h0 = __float2bfloat16(y0), h1 = __float2bfloat16(y1);
        bf16 h2 = __float2bfloat16(y2), h3 = __float2bfloat16(y3);
        *(__nv_bfloat162*)(oh + o)     = __nv_bfloat162(h0, h1);
        *(__nv_bfloat162*)(oh + o + 2) = __nv_bfloat162(h2, h3);
        *(__nv_bfloat162*)(ol + o) = __nv_bfloat162(
            __float2bfloat16(y0 - __bfloat162float(h0)),
            __float2bfloat16(y1 - __bfloat162float(h1)));
        *(__nv_bfloat162*)(ol + o + 2) = __nv_bfloat162(
            __float2bfloat16(y2 - __bfloat162float(h2)),
            __float2bfloat16(y3 - __bfloat162float(h3)));
    }
    if (o16) {
        *(__half2*)(o16 + o)     = __half2(__float2half(y0), __float2half(y1));
        *(__half2*)(o16 + o + 2) = __half2(__float2half(y2), __float2half(y3));
    }
    if (oc1) {
        const float4 w1v = ((const float4*)w1)[tid];
        const float4 w2v = ((const float4*)w2)[tid];
        float t1 = y0*w1v.x + y1*w1v.y + y2*w1v.z + y3*w1v.w;
        float t2 = y0*w2v.x + y1*w2v.y + y2*w2v.z + y3*w2v.w;
        t1 = brSum(t1, sh);
        t2 = brSum(t2, sh);
        if (tid == 0) { oc1[row] = t1; oc2[row] = t2; }
    }
}

// ------------------------------ softmax (vectorized, fp16 out) ---------------
__global__ void __launch_bounds__(256) softmax_kernel(
    const float* __restrict__ S, __half* __restrict__ o16)
{
    __shared__ float sh[32];
    const long long row = blockIdx.x;
    const float4* p4 = (const float4*)(S + row * (long long)SEQ);
    const int tid = threadIdx.x;
    float4 a = p4[tid], b = p4[tid + 256];
    float vals[8] = {a.x, a.y, a.z, a.w, b.x, b.y, b.z, b.w};
    float m = -1e30f;
    #pragma unroll
    for (int i = 0; i < 8; i++) m = fmaxf(m, vals[i]);
    m = brMax(m, sh);
    float s = 0.f;
    #pragma unroll
    for (int i = 0; i < 8; i++) { vals[i] = __expf(vals[i] - m); s += vals[i]; }
    s = brSum(s, sh);
    const float inv = 1.0f/s;
    __half* po = o16 + row*SEQ;
    *(__half2*)(po + tid*4)        = __half2(__float2half(vals[0]*inv), __float2half(vals[1]*inv));
    *(__half2*)(po + tid*4 + 2)    = __half2(__float2half(vals[2]*inv), __float2half(vals[3]*inv));
    *(__half2*)(po + 1024 + tid*4)     = __half2(__float2half(vals[4]*inv), __float2half(vals[5]*inv));
    *(__half2*)(po + 1024 + tid*4 + 2) = __half2(__float2half(vals[6]*inv), __float2half(vals[7]*inv));
}

// --------- merged: fp32 -> bf16 hi/lo split for Wq and Wk in one launch ------
__global__ void __launch_bounds__(256) conv_split2(
    const float* __restrict__ inA, bf16* __restrict__ ohA, bf16* __restrict__ olA,
    const float* __restrict__ inB, bf16* __restrict__ ohB, bf16* __restrict__ olB)
{
    const bool second = blockIdx.x >= 1024;
    const float* in = second ? inB : inA;
    bf16* oh = second ? ohB : ohA;
    bf16* ol = second ? olB : olA;
    const long long i = (long long)(blockIdx.x & 1023) * 1024 + threadIdx.x * 4;
    const float4 t = *(const float4*)(in + i);
    float v[4] = {t.x, t.y, t.z, t.w};
    #pragma unroll
    for (int j = 0; j < 4; ++j) {
        bf16 h = __float2bfloat16(v[j]);
        oh[i + j] = h;
        ol[i + j] = __float2bfloat16(v[j] - __bfloat162float(h));
    }
}

// ------- merged: transpose fp32 [1024,1024] -> fp16 for Wv and Wfc -----------
__global__ void __launch_bounds__(256) tr_half2(
    const float* __restrict__ inA, __half* __restrict__ outA,
    const float* __restrict__ inB, __half* __restrict__ outB)
{
    __shared__ float t[32][33];
    const bool second = blockIdx.z >= 1;
    const float* in = second ? inB : inA;
    __half* out = second ? outB : outA;
    const int C = 1024, R = 1024;
    const int c0 = blockIdx.x*32, r0 = blockIdx.y*32;
    const int tx = threadIdx.x & 31, ty = threadIdx.x >> 5;
    #pragma unroll
    for (int i = 0; i < 4; i++)
        t[ty + i*8][tx] = in[(long long)(r0 + ty + i*8)*C + c0 + tx];
    __syncthreads();
    #pragma unroll
    for (int i = 0; i < 4; i++)
        out[(long long)(c0 + ty + i*8)*R + r0 + tx] = __float2half(t[tx][ty + i*8]);
}

// ------- merged bias prep: w1 = Wq@bk, w2 = Wk@bq, c3 = bq.bk ----------------
__global__ void __launch_bounds__(256) bias_prep(
    const float* __restrict__ Wq, const float* __restrict__ Wk,
    const float* __restrict__ bq, const float* __restrict__ bk,
    float* __restrict__ w1, float* __restrict__ w2, float* __restrict__ c3)
{
    __shared__ float sh[32];
    const int tid = threadIdx.x;
    const int bid = blockIdx.x;          // 0..2048
    const float *va, *vb;
    float* out;
    if (bid < 1024)      { va = Wq + (long long)bid * 1024;            vb = bk; out = w1 + bid; }
    else if (bid < 2048) { va = Wk + (long long)(bid - 1024) * 1024;   vb = bq; out = w2 + (bid - 1024); }
    else                 { va = bq;                                    vb = bk; out = c3; }
    float s = 0.f;
    #pragma unroll
    for (int i = 0; i < 4; i++) {
        int c = tid + i*256;
        s += va[c] * vb[c];
    }
    s = brSum(s, sh);
    if (tid == 0) *out = s;
}

// ------------------------------ launcher -------------------------------------
static cudaStream_t g_s2 = nullptr;
static cudaEvent_t  g_evF = nullptr, g_evJ = nullptr;

extern "C" void kernel_launch(void* const* d_in, const int* in_sizes, int n_in,
                              void* d_out, int out_size)
{
    const float* x   = (const float*)d_in[0];
    const float* Wq  = (const float*)d_in[1];
    const float* bq  = (const float*)d_in[2];
    const float* Wk  = (const float*)d_in[3];
    const float* bk  = (const float*)d_in[4];
    const float* Wv  = (const float*)d_in[5];
    const float* bv  = (const float*)d_in[6];
    const float* Wfc = (const float*)d_in[7];
    const float* bfc = (const float*)d_in[8];
    const float* g1  = (const float*)d_in[9];
    const float* b1  = (const float*)d_in[10];
    const float* g2  = (const float*)d_in[11];
    const float* b2  = (const float*)d_in[12];
    float* y = (float*)d_out;

    if (!g_s2) {
        cudaStreamCreateWithFlags(&g_s2, cudaStreamNonBlocking);
        cudaEventCreateWithFlags(&g_evF, cudaEventDisableTiming);
        cudaEventCreateWithFlags(&g_evJ, cudaEventDisableTiming);
    }

    bf16 *wqsh,*wqsl,*wksh,*wksl,*mth,*mtl,*hh,*hl,*gh,*gl;
    __half *wvt,*wft,*h16,*vt16,*p16;
    float *s,*o,*zero,*w1,*w2,*c1,*c2,*c3;
    cudaGetSymbolAddress((void**)&wqsh, g_wqsh); cudaGetSymbolAddress((void**)&wqsl, g_wqsl);
    cudaGetSymbolAddress((void**)&wksh, g_wksh); cudaGetSymbolAddress((void**)&wksl, g_wksl);
    cudaGetSymbolAddress((void**)&mth, g_mth);   cudaGetSymbolAddress((void**)&mtl, g_mtl);
    cudaGetSymbolAddress((void**)&wvt, g_wvt);   cudaGetSymbolAddress((void**)&wft, g_wft);
    cudaGetSymbolAddress((void**)&hh, g_hh);     cudaGetSymbolAddress((void**)&hl, g_hl);
    cudaGetSymbolAddress((void**)&h16, g_h16);
    cudaGetSymbolAddress((void**)&gh, g_gh);     cudaGetSymbolAddress((void**)&gl, g_gl);
    cudaGetSymbolAddress((void**)&vt16, g_vt16);
    cudaGetSymbolAddress((void**)&p16, g_p16);
    cudaGetSymbolAddress((void**)&s, g_s);
    cudaGetSymbolAddress((void**)&o, g_o);
    cudaGetSymbolAddress((void**)&zero, g_zero);
    cudaGetSymbolAddress((void**)&w1, g_w1);     cudaGetSymbolAddress((void**)&w2, g_w2);
    cudaGetSymbolAddress((void**)&c1, g_c1);     cudaGetSymbolAddress((void**)&c2, g_c2);
    cudaGetSymbolAddress((void**)&c3, g_c3);

    cudaFuncSetAttribute(mm_hmma<2>, cudaFuncAttributeMaxDynamicSharedMemorySize, SMB3);
    cudaFuncSetAttribute(mm_hmma<4>, cudaFuncAttributeMaxDynamicSharedMemorySize, SMB3);
    cudaFuncSetAttribute(mm_fp16<0>, cudaFuncAttributeMaxDynamicSharedMemorySize, SMB1);
    cudaFuncSetAttribute(mm_fp16<3>, cudaFuncAttributeMaxDynamicSharedMemorySize, SMB1);
    cudaFuncSetAttribute(mm_fp16<5>, cudaFuncAttributeMaxDynamicSharedMemorySize, SMB1);

    const long long strQKV = (long long)SEQ*EMB;
    const long long strS   = (long long)SEQ*SEQ;

    // ---- fork: weight/M prep on s2, LN1 + Wv/Wfc transposes on main ----
    cudaEventRecord(g_evF, 0);
    cudaStreamWaitEvent(g_s2, g_evF, 0);

    // s2: Wq/Wk split -> bias terms -> M^T = Wk @ Wq^T (split)
    conv_split2<<<2048, 256, 0, g_s2>>>(Wq, wqsh, wqsl, Wk, wksh, wksl);
    bias_prep<<<2049, 256, 0, g_s2>>>(Wq, Wk, bq, bk, w1, w2, c3);
    mm_hmma<2><<<dim3(16,8,1), 256, SMB3, g_s2>>>(wksh, wksl, wqsh, wqsl, zero,
                                                  nullptr, nullptr, nullptr,
                                                  nullptr, mth, mtl, EMB, EMB, 0, 0, 0);
    cudaEventRecord(g_evJ, g_s2);

    // main: Wv/Wfc transpose + LN1 (fused c1/c2)
    tr_half2<<<dim3(32,32,2), 256>>>(Wv, wvt, Wfc, wft);
    ln_kernel<<<MTOT, 256>>>(x, g1, b1, hh, hl, h16, w1, w2, c1, c2);
    // NOTE: LN1's c1/c2 use w1/w2 from s2's bias_prep — but both are exactly
    // zero-products of zero biases only when bq=bk=0; to be safe order-wise,
    // c1/c2 must be produced AFTER w1/w2. Enforce by joining before LN1's
    // consumers AND by placing the join before anything reading c1/c2/M.
    cudaStreamWaitEvent(0, g_evJ, 0);

    // g = h @ M  (B operand = M^T), split out
    mm_hmma<2><<<dim3(16,128,1), 256, SMB3>>>(hh, hl, mth, mtl, zero,
                                              nullptr, nullptr, nullptr,
                                              nullptr, gh, gl, EMB, EMB, 0, 0, 0);
    // v-proj: fp16, fused transpose -> vt16 [B][EMB][SEQ]
    mm_fp16<5><<<dim3(16,128,1), 256, SMB1>>>(h16, wvt, bv, nullptr, nullptr, vt16,
                                              EMB, EMB, 0, 0, 0);
    // re-run the tiny c1/c2 reduction AFTER join so it reads valid w1/w2
    // (LN1 above already wrote c1/c2 possibly racing w1/w2; recompute cheaply)
    ln_kernel<<<MTOT, 256>>>(x, g1, b1, nullptr, nullptr, nullptr, w1, w2, c1, c2);
    // scores = g @ h^T + c1[row] + c2[col] + c3   (batched)
    mm_hmma<4><<<dim3(32,16,BATCH), 256, SMB3>>>(gh, gl, hh, hl, nullptr,
                                                 c1, c2, c3,
                                                 s, nullptr, nullptr, SEQ, EMB,
                                                 strQKV, strQKV, strS);
    // softmax -> fp16 probs
    softmax_kernel<<<MTOT, 256>>>(s, p16);
    // o = probs @ v: fp16 (batched), B operand = vt16
    mm_fp16<0><<<dim3(16,16,BATCH), 256, SMB1>>>(p16, vt16, nullptr, nullptr, o, nullptr,
                                                 EMB, SEQ, strS, strQKV, strQKV);
    // LN2 -> fp16 only
    ln_kernel<<<MTOT, 256>>>(o, g2, b2, nullptr, nullptr, h16,
                             nullptr, nullptr, nullptr, nullptr);
    // y = 2*(h2 @ Wfc + bfc + x): fp16
    mm_fp16<3><<<dim3(16,128,1), 256, SMB1>>>(h16, wft, bfc, x, y, nullptr,
                                              EMB, EMB, 0, 0, 0);
}

// round 16
// speedup vs baseline: 1.0666x; 1.0666x over previous
#include <cuda_runtime.h>
#include <cuda_bf16.h>
#include <cuda_fp16.h>
#include <cstdint>

#define BATCH 8
#define SEQ   2048
#define EMB   1024
#define MTOT  (BATCH*SEQ)   // 16384
typedef __nv_bfloat16 bf16;

// ------------------------------ scratch --------------------------------------
#define DA __device__ __align__(256)
DA bf16 g_wqsh[1024*1024], g_wqsl[1024*1024];       // Wq split (no transpose)
DA bf16 g_wksh[1024*1024], g_wksl[1024*1024];       // Wk split
DA bf16 g_mth[1024*1024],  g_mtl[1024*1024];        // (Wq Wk^T)^T split
DA __half g_wvt[1024*1024];                         // Wv^T fp16
DA __half g_wft[1024*1024];                         // Wfc^T fp16
DA bf16 g_hh[(size_t)MTOT*EMB],  g_hl[(size_t)MTOT*EMB];
DA __half g_h16[(size_t)MTOT*EMB];                  // LN out fp16 (reused LN1/LN2)
DA bf16 g_gh[(size_t)MTOT*EMB],  g_gl[(size_t)MTOT*EMB];  // g = h@M split
DA __half g_vt16[(size_t)MTOT*EMB];                 // v^T fp16 [B][EI][S]
DA float g_s[(size_t)BATCH*SEQ*SEQ];
DA __half g_p16[(size_t)BATCH*SEQ*SEQ];             // probs fp16
DA float g_o[(size_t)MTOT*EMB];
DA float g_zero[2048];                              // zero-initialized
DA float g_w1[1024], g_w2[1024];                    // Wq@bk, Wk@bq
DA float g_c1[MTOT], g_c2[MTOT];                    // h@w1, h@w2
DA float g_c3[1];                                   // bq.bk

// ------------------------------ helpers --------------------------------------
__device__ __forceinline__ uint32_t smem_u32(const void* p) {
    uint32_t a;
    asm("{ .reg .u64 t; cvta.to.shared.u64 t, %1; cvt.u32.u64 %0, t; }" : "=r"(a) : "l"(p));
    return a;
}
__device__ __forceinline__ void ldsm4(uint32_t* r, uint32_t addr) {
    asm volatile("ldmatrix.sync.aligned.m8n8.x4.shared.b16 {%0,%1,%2,%3}, [%4];"
        : "=r"(r[0]), "=r"(r[1]), "=r"(r[2]), "=r"(r[3]) : "r"(addr));
}
__device__ __forceinline__ void mma_bf(float* d, const uint32_t* a, uint32_t b0, uint32_t b1) {
    asm volatile("mma.sync.aligned.m16n8k16.row.col.f32.bf16.bf16.f32 "
        "{%0,%1,%2,%3},{%4,%5,%6,%7},{%8,%9},{%0,%1,%2,%3};"
        : "+f"(d[0]), "+f"(d[1]), "+f"(d[2]), "+f"(d[3])
        : "r"(a[0]), "r"(a[1]), "r"(a[2]), "r"(a[3]), "r"(b0), "r"(b1));
}
__device__ __forceinline__ void mma_fp(float* d, const uint32_t* a, uint32_t b0, uint32_t b1) {
    asm volatile("mma.sync.aligned.m16n8k16.row.col.f32.f16.f16.f32 "
        "{%0,%1,%2,%3},{%4,%5,%6,%7},{%8,%9},{%0,%1,%2,%3};"
        : "+f"(d[0]), "+f"(d[1]), "+f"(d[2]), "+f"(d[3])
        : "r"(a[0]), "r"(a[1]), "r"(a[2]), "r"(a[3]), "r"(b0), "r"(b1));
}

static constexpr int PITCH = 80;
static constexpr int ATILE = 128*PITCH;
static constexpr int BTILE = 64*PITCH;
static constexpr int STG3  = 2*ATILE + 2*BTILE;  // 30720 per stage
static constexpr int NSTAGE = 3;
static constexpr int SMB3  = NSTAGE*STG3;        // 92160
static constexpr int STG1  = ATILE + BTILE;      // 15360
static constexpr int SMB1  = NSTAGE*STG1;        // 46080

// =============================== mm3: bf16 3-term split =======================
// C[128x64 per CTA] = (A0+A1) @ (B0+B1)^T via hi*hi + hi*lo + lo*hi.
// 3-stage cp.async pipeline, ONE __syncthreads per K-chunk.
// EPI: 0 -> Cf=acc | 2 -> split(acc+bias)->Ch,Cl | 4 -> Cf=acc+r1[row]+r2[col]+c3
template<int EPI>
__global__ void __launch_bounds__(256, 2) mm_hmma(
    const bf16* __restrict__ A0, const bf16* __restrict__ A1,
    const bf16* __restrict__ B0, const bf16* __restrict__ B1,
    const float* __restrict__ bias,
    const float* __restrict__ r1, const float* __restrict__ r2,
    const float* __restrict__ c3p,
    float* __restrict__ Cf, bf16* __restrict__ Ch, bf16* __restrict__ Cl,
    int N, int K, long long sA, long long sB, long long sC)
{
    extern __shared__ char sm[];
    const int tid = threadIdx.x, lane = tid & 31, warp = tid >> 5;
    const long long bz = blockIdx.z;
    const int row0 = blockIdx.y * 128, col0 = blockIdx.x * 64;
    const bf16* srcs[4] = {
        A0 + sA*bz + (long long)row0*K,
        A1 + sA*bz + (long long)row0*K,
        B0 + sB*bz + (long long)col0*K,
        B1 + sB*bz + (long long)col0*K };
    const uint32_t sb = smem_u32(sm);

    auto stage_load = [&](int c, int buf) {
        const int k0 = c * 32;
        const uint32_t db = sb + buf * STG3;
        #pragma unroll
        for (int i = 0; i < 4; ++i) {            // A0,A1
            int idx  = tid + i * 256;
            int tile = idx >> 9;
            int row  = (idx >> 2) & 127;
            int ch   = idx & 3;
            const bf16* s = srcs[tile] + (long long)row * K + k0 + ch * 8;
            uint32_t d = db + tile * ATILE + row * PITCH + ch * 16;
            asm volatile("cp.async.cg.shared.global [%0], [%1], 16;" :: "r"(d), "l"(s));
        }
        #pragma unroll
        for (int i = 0; i < 2; ++i) {            // B0,B1
            int j    = tid + i * 256;
            int tile = j >> 8;
            int row  = (j >> 2) & 63;
            int ch   = j & 3;
            const bf16* s = srcs[2 + tile] + (long long)row * K + k0 + ch * 8;
            uint32_t d = db + 2*ATILE + tile * BTILE + row * PITCH + ch * 16;
            asm volatile("cp.async.cg.shared.global [%0], [%1], 16;" :: "r"(d), "l"(s));
        }
        asm volatile("cp.async.commit_group;" ::: "memory");
    };

    const int wr = (warp & 3) * 32;
    const int wc = (warp >> 2) * 32;
    float acc[2][4][4] = {};

    const int rA = lane & 15;
    const int byA = (lane >> 4) * 16;
    const int rB = (lane & 7) + ((lane >> 3) & 1) * 8;
    const int byB = ((lane >> 4) & 1) * 16;

    const int nch = K >> 5;                       // >= 2 for all our shapes
    stage_load(0, 0);
    stage_load(1, 1);
    int buf = 0;
    for (int c = 0; c < nch; ++c) {
        if (c + 1 < nch) {
            asm volatile("cp.async.wait_group 1;" ::: "memory");
        } else {
            asm volatile("cp.async.wait_group 0;" ::: "memory");
        }
        __syncthreads();
        if (c + 2 < nch) {
            int nb = buf + 2; if (nb >= NSTAGE) nb -= NSTAGE;
            stage_load(c + 2, nb);
        }
        const uint32_t base = sb + buf * STG3;
        #pragma unroll
        for (int ks = 0; ks < 2; ++ks) {
            const int kb = ks * 32;
            uint32_t ah[2][4], al[2][4], bh[2][4], bl[2][4];
            #pragma unroll
            for (int mi = 0; mi < 2; ++mi) {
                ldsm4(ah[mi], base + (wr + mi*16 + rA) * PITCH + byA + kb);
                ldsm4(al[mi], base + ATILE + (wr + mi*16 + rA) * PITCH + byA + kb);
            }
            #pragma unroll
            for (int ng = 0; ng < 2; ++ng) {
                ldsm4(bh[ng], base + 2*ATILE + (wc + ng*16 + rB) * PITCH + byB + kb);
                ldsm4(bl[ng], base + 2*ATILE + BTILE + (wc + ng*16 + rB) * PITCH + byB + kb);
            }
            #pragma unroll
            for (int mi = 0; mi < 2; ++mi)
                #pragma unroll
                for (int nj = 0; nj < 4; ++nj) {
                    mma_bf(acc[mi][nj], ah[mi], bh[nj>>1][nj&1], bh[nj>>1][(nj&1)+2]);
                    mma_bf(acc[mi][nj], ah[mi], bl[nj>>1][nj&1], bl[nj>>1][(nj&1)+2]);
                    mma_bf(acc[mi][nj], al[mi], bh[nj>>1][nj&1], bh[nj>>1][(nj&1)+2]);
                }
        }
        if (++buf == NSTAGE) buf = 0;
    }

    const int rb = row0 + wr + (lane >> 2);
    const int cb = col0 + wc + (lane & 3) * 2;
    #pragma unroll
    for (int mi = 0; mi < 2; ++mi)
        #pragma unroll
        for (int h = 0; h < 2; ++h) {
            const int r = rb + mi * 16 + h * 8;
            #pragma unroll
            for (int nj = 0; nj < 4; ++nj) {
                const int colg = cb + nj * 8;
                const long long oi = sC * bz + (long long)r * N + colg;
                float v0 = acc[mi][nj][2*h], v1 = acc[mi][nj][2*h + 1];
                if (EPI == 0) {
                    *(float2*)(Cf + oi) = make_float2(v0, v1);
                } else if (EPI == 2) {
                    v0 += bias[colg]; v1 += bias[colg + 1];
                    bf16 h0 = __float2bfloat16(v0), h1 = __float2bfloat16(v1);
                    bf16 l0 = __float2bfloat16(v0 - __bfloat162float(h0));
                    bf16 l1 = __float2bfloat16(v1 - __bfloat162float(h1));
                    *(__nv_bfloat162*)(Ch + oi) = __nv_bfloat162(h0, h1);
                    *(__nv_bfloat162*)(Cl + oi) = __nv_bfloat162(l0, l1);
                } else {  // EPI == 4 (scores with rank-1 bias terms)
                    const float base_add = r1[bz*N + r] + c3p[0];
                    *(float2*)(Cf + oi) = make_float2(
                        v0 + base_add + r2[bz*N + colg],
                        v1 + base_add + r2[bz*N + colg + 1]);
                }
            }
        }
}

// =============================== mm1: fp16 single-term ========================
// 3-stage pipeline, one sync per chunk.
// EPI: 0 -> Cf=acc | 1 -> Cf=acc+bias | 3 -> Cf=2*(acc+bias+X)
// EPI: 5 -> fp16 TRANSPOSED out: Ct[b][col][row_local] = acc+bias (v-proj fused v^T)
template<int EPI>
__global__ void __launch_bounds__(256, 2) mm_fp16(
    const __half* __restrict__ A, const __half* __restrict__ B,
    const float* __restrict__ bias, const float* __restrict__ X,
    float* __restrict__ Cf, __half* __restrict__ Ct,
    int N, int K, long long sA, long long sB, long long sC)
{
    extern __shared__ char sm[];
    const int tid = threadIdx.x, lane = tid & 31, warp = tid >> 5;
    const long long bz = blockIdx.z;
    const int row0 = blockIdx.y * 128, col0 = blockIdx.x * 64;
    const __half* srcA = A + sA*bz + (long long)row0*K;
    const __half* srcB = B + sB*bz + (long long)col0*K;
    const uint32_t sb = smem_u32(sm);

    auto stage_load = [&](int c, int buf) {
        const int k0 = c * 32;
        const uint32_t db = sb + buf * STG1;
        #pragma unroll
        for (int i = 0; i < 2; ++i) {
            int idx = tid + i * 256;
            int row = (idx >> 2) & 127;
            int ch  = idx & 3;
            const __half* s = srcA + (long long)row * K + k0 + ch * 8;
            uint32_t d = db + row * PITCH + ch * 16;
            asm volatile("cp.async.cg.shared.global [%0], [%1], 16;" :: "r"(d), "l"(s));
        }
        {
            int row = (tid >> 2) & 63;
            int ch  = tid & 3;
            const __half* s = srcB + (long long)row * K + k0 + ch * 8;
            uint32_t d = db + ATILE + row * PITCH + ch * 16;
            asm volatile("cp.async.cg.shared.global [%0], [%1], 16;" :: "r"(d), "l"(s));
        }
        asm volatile("cp.async.commit_group;" ::: "memory");
    };

    const int wr = (warp & 3) * 32;
    const int wc = (warp >> 2) * 32;
    float acc[2][4][4] = {};

    const int rA = lane & 15;
    const int byA = (lane >> 4) * 16;
    const int rB = (lane & 7) + ((lane >> 3) & 1) * 8;
    const int byB = ((lane >> 4) & 1) * 16;

    const int nch = K >> 5;
    stage_load(0, 0);
    stage_load(1, 1);
    int buf = 0;
    for (int c = 0; c < nch; ++c) {
        if (c + 1 < nch) {
            asm volatile("cp.async.wait_group 1;" ::: "memory");
        } else {
            asm volatile("cp.async.wait_group 0;" ::: "memory");
        }
        __syncthreads();
        if (c + 2 < nch) {
            int nb = buf + 2; if (nb >= NSTAGE) nb -= NSTAGE;
            stage_load(c + 2, nb);
        }
        const uint32_t base = sb + buf * STG1;
        #pragma unroll
        for (int ks = 0; ks < 2; ++ks) {
            const int kb = ks * 32;
            uint32_t ah[2][4], bh[2][4];
            #pragma unroll
            for (int mi = 0; mi < 2; ++mi)
                ldsm4(ah[mi], base + (wr + mi*16 + rA) * PITCH + byA + kb);
            #pragma unroll
            for (int ng = 0; ng < 2; ++ng)
                ldsm4(bh[ng], base + ATILE + (wc + ng*16 + rB) * PITCH + byB + kb);
            #pragma unroll
            for (int mi = 0; mi < 2; ++mi)
                #pragma unroll
                for (int nj = 0; nj < 4; ++nj)
                    mma_fp(acc[mi][nj], ah[mi], bh[nj>>1][nj&1], bh[nj>>1][(nj&1)+2]);
        }
        if (++buf == NSTAGE) buf = 0;
    }

    const int rb = row0 + wr + (lane >> 2);
    const int cb = col0 + wc + (lane & 3) * 2;
    __half* st = (__half*)sm;   // EPI==5 staging: [64 cols][pitch 136 halves]
    if (EPI == 5) __syncthreads();   // all reads of last buffer done before reuse as staging
    #pragma unroll
    for (int mi = 0; mi < 2; ++mi)
        #pragma unroll
        for (int h = 0; h < 2; ++h) {
            const int r = rb + mi * 16 + h * 8;
            #pragma unroll
            for (int nj = 0; nj < 4; ++nj) {
                const int colg = cb + nj * 8;
                float v0 = acc[mi][nj][2*h], v1 = acc[mi][nj][2*h + 1];
                if (EPI == 5) {
                    const int lr = r - row0, lc = colg - col0;
                    st[lc * 136 + lr]       = __float2half(v0 + bias[colg]);
                    st[(lc + 1) * 136 + lr] = __float2half(v1 + bias[colg + 1]);
                } else {
                    const long long oi = sC * bz + (long long)r * N + colg;
                    if (EPI == 0) {
                        *(float2*)(Cf + oi) = make_float2(v0, v1);
                    } else if (EPI == 1) {
                        *(float2*)(Cf + oi) = make_float2(v0 + bias[colg], v1 + bias[colg+1]);
                    } else {
                        const float2 xb = *(const float2*)(X + oi);
                        *(float2*)(Cf + oi) = make_float2(2.0f*(v0 + bias[colg]   + xb.x),
                                                          2.0f*(v1 + bias[colg+1] + xb.y));
                    }
                }
            }
        }
    if (EPI == 5) {
        __syncthreads();
        const int b = row0 >> 11;               // 128-row tile lies in one batch
        const int s0 = row0 & 2047;
        #pragma unroll
        for (int i = 0; i < 4; ++i) {
            int ch = tid + i * 256;             // 1024 chunks of 8 halves
            int c = ch >> 4, off = (ch & 15) * 8;
            uint4 val = *(const uint4*)(st + c * 136 + off);
            *(uint4*)(Ct + ((long long)b * EMB + col0 + c) * SEQ + s0 + off) = val;
        }
    }
}

// ------------------------------ reductions -----------------------------------
__device__ __forceinline__ float brSum(float v, float* sh) {
    #pragma unroll
    for (int o = 16; o > 0; o >>= 1) v += __shfl_down_sync(0xffffffffu, v, o);
    int ln = threadIdx.x & 31, w = threadIdx.x >> 5;
    __syncthreads();
    if (ln == 0) sh[w] = v;
    __syncthreads();
    if (w == 0) {
        v = (ln < 8) ? sh[ln] : 0.0f;
        #pragma unroll
        for (int o = 4; o > 0; o >>= 1) v += __shfl_down_sync(0xffffffffu, v, o);
        if (ln == 0) sh[0] = v;
    }
    __syncthreads();
    return sh[0];
}
__device__ __forceinline__ float brMax(float v, float* sh) {
    #pragma unroll
    for (int o = 16; o > 0; o >>= 1) v = fmaxf(v, __shfl_down_sync(0xffffffffu, v, o));
    int ln = threadIdx.x & 31, w = threadIdx.x >> 5;
    __syncthreads();
    if (ln == 0) sh[w] = v;
    __syncthreads();
    if (w == 0) {
        v = (ln < 8) ? sh[ln] : -1e30f;
        #pragma unroll
        for (int o = 4; o > 0; o >>= 1) v = fmaxf(v, __shfl_down_sync(0xffffffffu, v, o));
        if (ln == 0) sh[0] = v;
    }
    __syncthreads();
    return sh[0];
}

// ------------------------------ LN (vectorized, optional fused matvecs) -------
__global__ void __launch_bounds__(256) ln_kernel(
    const float* __restrict__ x, const float* __restrict__ g,
    const float* __restrict__ b, bf16* __restrict__ oh, bf16* __restrict__ ol,
    __half* __restrict__ o16,
    const float* __restrict__ w1, const float* __restrict__ w2,
    float* __restrict__ oc1, float* __restrict__ oc2)
{
    __shared__ float sh[32];
    const long long row = blockIdx.x;
    const int tid = threadIdx.x;
    const float4 t = ((const float4*)(x + row*EMB))[tid];
    float s  = t.x + t.y + t.z + t.w;
    float s2 = t.x*t.x + t.y*t.y + t.z*t.z + t.w*t.w;
    s  = brSum(s,  sh);
    s2 = brSum(s2, sh);
    const float mu  = s * (1.0f/EMB);
    const float inv = rsqrtf(s2*(1.0f/EMB) - mu*mu + 1e-5f);
    const float4 gv = ((const float4*)g)[tid];
    const float4 bv = ((const float4*)b)[tid];
    float y0 = (t.x - mu)*inv*gv.x + bv.x;
    float y1 = (t.y - mu)*inv*gv.y + bv.y;
    float y2 = (t.z - mu)*inv*gv.z + bv.z;
    float y3 = (t.w - mu)*inv*gv.w + bv.w;
    const long long o = row*EMB + tid*4;
    if (oh) {
        bf16 h0 = __float2bfloat16(y0), h1 = __float2bfloat16(y1);
        bf16 h2 = __float2bfloat16(y2), h3 = __float2bfloat16(y3);
        *(__nv_bfloat162*)(oh + o)     = __nv_bfloat162(h0, h1);
        *(__nv_bfloat162*)(oh + o + 2) = __nv_bfloat162(h2, h3);
        *(__nv_bfloat162*)(ol + o) = __nv_bfloat162(
            __float2bfloat16(y0 - __bfloat162float(h0)),
            __float2bfloat16(y1 - __bfloat162float(h1)));
        *(__nv_bfloat162*)(ol + o + 2) = __nv_bfloat162(
            __float2bfloat16(y2 - __bfloat162float(h2)),
            __float2bfloat16(y3 - __bfloat162float(h3)));
    }
    if (o16) {
        *(__half2*)(o16 + o)     = __half2(__float2half(y0), __float2half(y1));
        *(__half2*)(o16 + o + 2) = __half2(__float2half(y2), __float2half(y3));
    }
    if (oc1) {
        const float4 w1v = ((const float4*)w1)[tid];
        const float4 w2v = ((const float4*)w2)[tid];
        float t1 = y0*w1v.x + y1*w1v.y + y2*w1v.z + y3*w1v.w;
        float t2 = y0*w2v.x + y1*w2v.y + y2*w2v.z + y3*w2v.w;
        t1 = brSum(t1, sh);
        t2 = brSum(t2, sh);
        if (tid == 0) { oc1[row] = t1; oc2[row] = t2; }
    }
}

// ------------------------------ softmax (vectorized, fp16 out) ---------------
__global__ void __launch_bounds__(256) softmax_kernel(
    const float* __restrict__ S, __half* __restrict__ o16)
{
    __shared__ float sh[32];
    const long long row = blockIdx.x;
    const float4* p4 = (const float4*)(S + row * (long long)SEQ);
    const int tid = threadIdx.x;
    float4 a = p4[tid], b = p4[tid + 256];
    float vals[8] = {a.x, a.y, a.z, a.w, b.x, b.y, b.z, b.w};
    float m = -1e30f;
    #pragma unroll
    for (int i = 0; i < 8; i++) m = fmaxf(m, vals[i]);
    m = brMax(m, sh);
    float s = 0.f;
    #pragma unroll
    for (int i = 0; i < 8; i++) { vals[i] = __expf(vals[i] - m); s += vals[i]; }
    s = brSum(s, sh);
    const float inv = 1.0f/s;
    __half* po = o16 + row*SEQ;
    *(__half2*)(po + tid*4)        = __half2(__float2half(vals[0]*inv), __float2half(vals[1]*inv));
    *(__half2*)(po + tid*4 + 2)    = __half2(__float2half(vals[2]*inv), __float2half(vals[3]*inv));
    *(__half2*)(po + 1024 + tid*4)     = __half2(__float2half(vals[4]*inv), __float2half(vals[5]*inv));
    *(__half2*)(po + 1024 + tid*4 + 2) = __half2(__float2half(vals[6]*inv), __float2half(vals[7]*inv));
}

// --------- merged: fp32 -> bf16 hi/lo split for Wq and Wk in one launch ------
__global__ void __launch_bounds__(256) conv_split2(
    const float* __restrict__ inA, bf16* __restrict__ ohA, bf16* __restrict__ olA,
    const float* __restrict__ inB, bf16* __restrict__ ohB, bf16* __restrict__ olB)
{
    const bool second = blockIdx.x >= 1024;
    const float* in = second ? inB : inA;
    bf16* oh = second ? ohB : ohA;
    bf16* ol = second ? olB : olA;
    const long long i = (long long)(blockIdx.x & 1023) * 1024 + threadIdx.x * 4;
    const float4 t = *(const float4*)(in + i);
    float v[4] = {t.x, t.y, t.z, t.w};
    #pragma unroll
    for (int j = 0; j < 4; ++j) {
        bf16 h = __float2bfloat16(v[j]);
        oh[i + j] = h;
        ol[i + j] = __float2bfloat16(v[j] - __bfloat162float(h));
    }
}

// ------- merged: transpose fp32 [1024,1024] -> fp16 for Wv and Wfc -----------
__global__ void __launch_bounds__(256) tr_half2(
    const float* __restrict__ inA, __half* __restrict__ outA,
    const float* __restrict__ inB, __half* __restrict__ outB)
{
    __shared__ float t[32][33];
    const bool second = blockIdx.z >= 1;
    const float* in = second ? inB : inA;
    __half* out = second ? outB : outA;
    const int C = 1024, R = 1024;
    const int c0 = blockIdx.x*32, r0 = blockIdx.y*32;
    const int tx = threadIdx.x & 31, ty = threadIdx.x >> 5;
    #pragma unroll
    for (int i = 0; i < 4; i++)
        t[ty + i*8][tx] = in[(long long)(r0 + ty + i*8)*C + c0 + tx];
    __syncthreads();
    #pragma unroll
    for (int i = 0; i < 4; i++)
        out[(long long)(c0 + ty + i*8)*R + r0 + tx] = __float2half(t[tx][ty + i*8]);
}

// ------- merged bias prep: w1 = Wq@bk, w2 = Wk@bq, c3 = bq.bk ----------------
__global__ void __launch_bounds__(256) bias_prep(
    const float* __restrict__ Wq, const float* __restrict__ Wk,
    const float* __restrict__ bq, const float* __restrict__ bk,
    float* __restrict__ w1, float* __restrict__ w2, float* __restrict__ c3)
{
    __shared__ float sh[32];
    const int tid = threadIdx.x;
    const int bid = blockIdx.x;          // 0..2048
    const float *va, *vb;
    float* out;
    if (bid < 1024)      { va = Wq + (long long)bid * 1024;            vb = bk; out = w1 + bid; }
    else if (bid < 2048) { va = Wk + (long long)(bid - 1024) * 1024;   vb = bq; out = w2 + (bid - 1024); }
    else                 { va = bq;                                    vb = bk; out = c3; }
    float s = 0.f;
    #pragma unroll
    for (int i = 0; i < 4; i++) {
        int c = tid + i*256;
        s += va[c] * vb[c];
    }
    s = brSum(s, sh);
    if (tid == 0) *out = s;
}

// ------------------------------ launcher -------------------------------------
extern "C" void kernel_launch(void* const* d_in, const int* in_sizes, int n_in,
                              void* d_out, int out_size)
{
    const float* x   = (const float*)d_in[0];
    const float* Wq  = (const float*)d_in[1];
    const float* bq  = (const float*)d_in[2];
    const float* Wk  = (const float*)d_in[3];
    const float* bk  = (const float*)d_in[4];
    const float* Wv  = (const float*)d_in[5];
    const float* bv  = (const float*)d_in[6];
    const float* Wfc = (const float*)d_in[7];
    const float* bfc = (const float*)d_in[8];
    const float* g1  = (const float*)d_in[9];
    const float* b1  = (const float*)d_in[10];
    const float* g2  = (const float*)d_in[11];
    const float* b2  = (const float*)d_in[12];
    float* y = (float*)d_out;

    bf16 *wqsh,*wqsl,*wksh,*wksl,*mth,*mtl,*hh,*hl,*gh,*gl;
    __half *wvt,*wft,*h16,*vt16,*p16;
    float *s,*o,*zero,*w1,*w2,*c1,*c2,*c3;
    cudaGetSymbolAddress((void**)&wqsh, g_wqsh); cudaGetSymbolAddress((void**)&wqsl, g_wqsl);
    cudaGetSymbolAddress((void**)&wksh, g_wksh); cudaGetSymbolAddress((void**)&wksl, g_wksl);
    cudaGetSymbolAddress((void**)&mth, g_mth);   cudaGetSymbolAddress((void**)&mtl, g_mtl);
    cudaGetSymbolAddress((void**)&wvt, g_wvt);   cudaGetSymbolAddress((void**)&wft, g_wft);
    cudaGetSymbolAddress((void**)&hh, g_hh);     cudaGetSymbolAddress((void**)&hl, g_hl);
    cudaGetSymbolAddress((void**)&h16, g_h16);
    cudaGetSymbolAddress((void**)&gh, g_gh);     cudaGetSymbolAddress((void**)&gl, g_gl);
    cudaGetSymbolAddress((void**)&vt16, g_vt16);
    cudaGetSymbolAddress((void**)&p16, g_p16);
    cudaGetSymbolAddress((void**)&s, g_s);
    cudaGetSymbolAddress((void**)&o, g_o);
    cudaGetSymbolAddress((void**)&zero, g_zero);
    cudaGetSymbolAddress((void**)&w1, g_w1);     cudaGetSymbolAddress((void**)&w2, g_w2);
    cudaGetSymbolAddress((void**)&c1, g_c1);     cudaGetSymbolAddress((void**)&c2, g_c2);
    cudaGetSymbolAddress((void**)&c3, g_c3);

    cudaFuncSetAttribute(mm_hmma<2>, cudaFuncAttributeMaxDynamicSharedMemorySize, SMB3);
    cudaFuncSetAttribute(mm_hmma<4>, cudaFuncAttributeMaxDynamicSharedMemorySize, SMB3);
    cudaFuncSetAttribute(mm_fp16<0>, cudaFuncAttributeMaxDynamicSharedMemorySize, SMB1);
    cudaFuncSetAttribute(mm_fp16<3>, cudaFuncAttributeMaxDynamicSharedMemorySize, SMB1);
    cudaFuncSetAttribute(mm_fp16<5>, cudaFuncAttributeMaxDynamicSharedMemorySize, SMB1);

    const long long strQKV = (long long)SEQ*EMB;
    const long long strS   = (long long)SEQ*SEQ;

    // weight prep (merged launches)
    conv_split2<<<2048, 256>>>(Wq, wqsh, wqsl, Wk, wksh, wksl);
    tr_half2<<<dim3(32,32,2), 256>>>(Wv, wvt, Wfc, wft);
    bias_prep<<<2049, 256>>>(Wq, Wk, bq, bk, w1, w2, c3);
    // M^T = Wk @ Wq^T, split  (M = Wq @ Wk^T)
    mm_hmma<2><<<dim3(16,8,1), 256, SMB3>>>(wksh, wksl, wqsh, wqsl, zero,
                                            nullptr, nullptr, nullptr,
                                            nullptr, mth, mtl, EMB, EMB, 0, 0, 0);
    // LN1 -> bf16 split + fp16, fused c1/c2
    ln_kernel<<<MTOT, 256>>>(x, g1, b1, hh, hl, h16, w1, w2, c1, c2);
    // g = h @ M  (B operand = M^T), split out
    mm_hmma<2><<<dim3(16,128,1), 256, SMB3>>>(hh, hl, mth, mtl, zero,
                                              nullptr, nullptr, nullptr,
                                              nullptr, gh, gl, EMB, EMB, 0, 0, 0);
    // v-proj: fp16, fused transpose -> vt16 [B][EMB][SEQ]
    mm_fp16<5><<<dim3(16,128,1), 256, SMB1>>>(h16, wvt, bv, nullptr, nullptr, vt16,
                                              EMB, EMB, 0, 0, 0);
    // scores = g @ h^T + c1[row] + c2[col] + c3   (batched)
    mm_hmma<4><<<dim3(32,16,BATCH), 256, SMB3>>>(gh, gl, hh, hl, nullptr,
                                                 c1, c2, c3,
                                                 s, nullptr, nullptr, SEQ, EMB,
                                                 strQKV, strQKV, strS);
    // softmax -> fp16 probs
    softmax_kernel<<<MTOT, 256>>>(s, p16);
    // o = probs @ v: fp16 (batched), B operand = vt16
    mm_fp16<0><<<dim3(16,16,BATCH), 256, SMB1>>>(p16, vt16, nullptr, nullptr, o, nullptr,
                                                 EMB, SEQ, strS, strQKV, strQKV);
    // LN2 -> fp16 only
    ln_kernel<<<MTOT, 256>>>(o, g2, b2, nullptr, nullptr, h16,
                             nullptr, nullptr, nullptr, nullptr);
    // y = 2*(h2 @ Wfc + bfc + x): fp16
    mm_fp16<3><<<dim3(16,128,1), 256, SMB1>>>(h16, wft, bfc, x, y, nullptr,
                                              EMB, EMB, 0, 0, 0);
}

// round 17
// speedup vs baseline: 1.1478x; 1.0761x over previous
#include <cuda_runtime.h>
#include <cuda_bf16.h>
#include <cuda_fp16.h>
#include <cstdint>

#define BATCH 8
#define SEQ   2048
#define EMB   1024
#define MTOT  (BATCH*SEQ)   // 16384
typedef __nv_bfloat16 bf16;

// ------------------------------ scratch --------------------------------------
#define DA __device__ __align__(256)
DA bf16 g_wqsh[1024*1024], g_wqsl[1024*1024];       // Wq split (no transpose)
DA bf16 g_wksh[1024*1024], g_wksl[1024*1024];       // Wk split
DA bf16 g_mth[1024*1024],  g_mtl[1024*1024];        // (Wq Wk^T)^T split
DA __half g_wvt[1024*1024];                         // Wv^T fp16
DA __half g_wft[1024*1024];                         // Wfc^T fp16
DA bf16 g_hh[(size_t)MTOT*EMB],  g_hl[(size_t)MTOT*EMB];
DA __half g_h16[(size_t)MTOT*EMB];                  // LN out fp16 (reused LN1/LN2)
DA bf16 g_gh[(size_t)MTOT*EMB],  g_gl[(size_t)MTOT*EMB];  // g = h@M split
DA __half g_vt16[(size_t)MTOT*EMB];                 // v^T fp16 [B][EI][S]
DA float g_s[(size_t)BATCH*SEQ*SEQ];
DA __half g_p16[(size_t)BATCH*SEQ*SEQ];             // probs fp16
DA float g_o[(size_t)MTOT*EMB];
DA float g_zero[2048];                              // zero-initialized
DA float g_w1[1024], g_w2[1024];                    // Wq@bk, Wk@bq
DA float g_c1[MTOT], g_c2[MTOT];                    // h@w1, h@w2
DA float g_c3[1];                                   // bq.bk

// ------------------------------ helpers --------------------------------------
__device__ __forceinline__ uint32_t smem_u32(const void* p) {
    uint32_t a;
    asm("{ .reg .u64 t; cvta.to.shared.u64 t, %1; cvt.u32.u64 %0, t; }" : "=r"(a) : "l"(p));
    return a;
}
__device__ __forceinline__ void ldsm4(uint32_t* r, uint32_t addr) {
    asm volatile("ldmatrix.sync.aligned.m8n8.x4.shared.b16 {%0,%1,%2,%3}, [%4];"
        : "=r"(r[0]), "=r"(r[1]), "=r"(r[2]), "=r"(r[3]) : "r"(addr));
}
__device__ __forceinline__ void mma_bf(float* d, const uint32_t* a, uint32_t b0, uint32_t b1) {
    asm volatile("mma.sync.aligned.m16n8k16.row.col.f32.bf16.bf16.f32 "
        "{%0,%1,%2,%3},{%4,%5,%6,%7},{%8,%9},{%0,%1,%2,%3};"
        : "+f"(d[0]), "+f"(d[1]), "+f"(d[2]), "+f"(d[3])
        : "r"(a[0]), "r"(a[1]), "r"(a[2]), "r"(a[3]), "r"(b0), "r"(b1));
}
__device__ __forceinline__ void mma_fp(float* d, const uint32_t* a, uint32_t b0, uint32_t b1) {
    asm volatile("mma.sync.aligned.m16n8k16.row.col.f32.f16.f16.f32 "
        "{%0,%1,%2,%3},{%4,%5,%6,%7},{%8,%9},{%0,%1,%2,%3};"
        : "+f"(d[0]), "+f"(d[1]), "+f"(d[2]), "+f"(d[3])
        : "r"(a[0]), "r"(a[1]), "r"(a[2]), "r"(a[3]), "r"(b0), "r"(b1));
}

// K-chunk = 64 (128-byte rows), pitch 144 keeps ldmatrix conflict-free
// (row phase (r*144)%128 = (r*16)%128 -> 8 distinct groups, same as pitch 80).
static constexpr int PITCH = 144;
static constexpr int ATILE = 128*PITCH;   // 18432
static constexpr int BTILE = 64*PITCH;    //  9216
static constexpr int STG3  = 2*ATILE + 2*BTILE;  // 55296 per stage
static constexpr int SMB3  = 2*STG3;             // 110592
static constexpr int STG1  = ATILE + BTILE;      // 27648
static constexpr int SMB1  = 2*STG1;             // 55296

// =============================== mm3: bf16 3-term split =======================
// C[128x64 per CTA] = (A0+A1) @ (B0+B1)^T via hi*hi + hi*lo + lo*hi.
// BK=64, 2-stage cp.async pipeline, ONE __syncthreads per K-chunk.
// EPI: 0 -> Cf=acc | 2 -> split(acc+bias)->Ch,Cl | 4 -> Cf=acc+r1[row]+r2[col]+c3
template<int EPI>
__global__ void __launch_bounds__(256, 2) mm_hmma(
    const bf16* __restrict__ A0, const bf16* __restrict__ A1,
    const bf16* __restrict__ B0, const bf16* __restrict__ B1,
    const float* __restrict__ bias,
    const float* __restrict__ r1, const float* __restrict__ r2,
    const float* __restrict__ c3p,
    float* __restrict__ Cf, bf16* __restrict__ Ch, bf16* __restrict__ Cl,
    int N, int K, long long sA, long long sB, long long sC)
{
    extern __shared__ char sm[];
    const int tid = threadIdx.x, lane = tid & 31, warp = tid >> 5;
    const long long bz = blockIdx.z;
    const int row0 = blockIdx.y * 128, col0 = blockIdx.x * 64;
    const bf16* srcs[4] = {
        A0 + sA*bz + (long long)row0*K,
        A1 + sA*bz + (long long)row0*K,
        B0 + sB*bz + (long long)col0*K,
        B1 + sB*bz + (long long)col0*K };
    const uint32_t sb = smem_u32(sm);

    auto stage_load = [&](int c, int buf) {
        const int k0 = c * 64;
        const uint32_t db = sb + buf * STG3;
        #pragma unroll
        for (int i = 0; i < 8; ++i) {            // A0,A1: 2048 16B chunks
            int idx  = tid + i * 256;
            int tile = idx >> 10;
            int row  = (idx >> 3) & 127;
            int ch   = idx & 7;
            const bf16* s = srcs[tile] + (long long)row * K + k0 + ch * 8;
            uint32_t d = db + tile * ATILE + row * PITCH + ch * 16;
            asm volatile("cp.async.cg.shared.global [%0], [%1], 16;" :: "r"(d), "l"(s));
        }
        #pragma unroll
        for (int i = 0; i < 4; ++i) {            // B0,B1: 1024 chunks
            int j    = tid + i * 256;
            int tile = j >> 9;
            int row  = (j >> 3) & 63;
            int ch   = j & 7;
            const bf16* s = srcs[2 + tile] + (long long)row * K + k0 + ch * 8;
            uint32_t d = db + 2*ATILE + tile * BTILE + row * PITCH + ch * 16;
            asm volatile("cp.async.cg.shared.global [%0], [%1], 16;" :: "r"(d), "l"(s));
        }
        asm volatile("cp.async.commit_group;" ::: "memory");
    };

    const int wr = (warp & 3) * 32;
    const int wc = (warp >> 2) * 32;
    float acc[2][4][4] = {};

    const int rA = lane & 15;
    const int byA = (lane >> 4) * 16;
    const int rB = (lane & 7) + ((lane >> 3) & 1) * 8;
    const int byB = ((lane >> 4) & 1) * 16;

    const int nch = K >> 6;                       // >= 2 for all our shapes
    stage_load(0, 0);
    for (int c = 0; c < nch; ++c) {
        const int buf = c & 1;
        asm volatile("cp.async.wait_group 0;" ::: "memory");
        __syncthreads();
        if (c + 1 < nch) stage_load(c + 1, buf ^ 1);
        const uint32_t base = sb + buf * STG3;
        #pragma unroll
        for (int ks = 0; ks < 4; ++ks) {
            const int kb = ks * 32;
            uint32_t ah[2][4], al[2][4], bh[2][4], bl[2][4];
            #pragma unroll
            for (int mi = 0; mi < 2; ++mi) {
                ldsm4(ah[mi], base + (wr + mi*16 + rA) * PITCH + byA + kb);
                ldsm4(al[mi], base + ATILE + (wr + mi*16 + rA) * PITCH + byA + kb);
            }
            #pragma unroll
            for (int ng = 0; ng < 2; ++ng) {
                ldsm4(bh[ng], base + 2*ATILE + (wc + ng*16 + rB) * PITCH + byB + kb);
                ldsm4(bl[ng], base + 2*ATILE + BTILE + (wc + ng*16 + rB) * PITCH + byB + kb);
            }
            #pragma unroll
            for (int mi = 0; mi < 2; ++mi)
                #pragma unroll
                for (int nj = 0; nj < 4; ++nj) {
                    mma_bf(acc[mi][nj], ah[mi], bh[nj>>1][nj&1], bh[nj>>1][(nj&1)+2]);
                    mma_bf(acc[mi][nj], ah[mi], bl[nj>>1][nj&1], bl[nj>>1][(nj&1)+2]);
                    mma_bf(acc[mi][nj], al[mi], bh[nj>>1][nj&1], bh[nj>>1][(nj&1)+2]);
                }
        }
    }

    const int rb = row0 + wr + (lane >> 2);
    const int cb = col0 + wc + (lane & 3) * 2;
    #pragma unroll
    for (int mi = 0; mi < 2; ++mi)
        #pragma unroll
        for (int h = 0; h < 2; ++h) {
            const int r = rb + mi * 16 + h * 8;
            #pragma unroll
            for (int nj = 0; nj < 4; ++nj) {
                const int colg = cb + nj * 8;
                const long long oi = sC * bz + (long long)r * N + colg;
                float v0 = acc[mi][nj][2*h], v1 = acc[mi][nj][2*h + 1];
                if (EPI == 0) {
                    *(float2*)(Cf + oi) = make_float2(v0, v1);
                } else if (EPI == 2) {
                    v0 += bias[colg]; v1 += bias[colg + 1];
                    bf16 h0 = __float2bfloat16(v0), h1 = __float2bfloat16(v1);
                    bf16 l0 = __float2bfloat16(v0 - __bfloat162float(h0));
                    bf16 l1 = __float2bfloat16(v1 - __bfloat162float(h1));
                    *(__nv_bfloat162*)(Ch + oi) = __nv_bfloat162(h0, h1);
                    *(__nv_bfloat162*)(Cl + oi) = __nv_bfloat162(l0, l1);
                } else {  // EPI == 4 (scores with rank-1 bias terms)
                    const float base_add = r1[bz*N + r] + c3p[0];
                    *(float2*)(Cf + oi) = make_float2(
                        v0 + base_add + r2[bz*N + colg],
                        v1 + base_add + r2[bz*N + colg + 1]);
                }
            }
        }
}

// =============================== mm1: fp16 single-term ========================
// BK=64, 2-stage pipeline, one sync per chunk.
// EPI: 0 -> Cf=acc | 1 -> Cf=acc+bias | 3 -> Cf=2*(acc+bias+X)
// EPI: 5 -> fp16 TRANSPOSED out: Ct[b][col][row_local] = acc+bias (v-proj fused v^T)
template<int EPI>
__global__ void __launch_bounds__(256, 2) mm_fp16(
    const __half* __restrict__ A, const __half* __restrict__ B,
    const float* __restrict__ bias, const float* __restrict__ X,
    float* __restrict__ Cf, __half* __restrict__ Ct,
    int N, int K, long long sA, long long sB, long long sC)
{
    extern __shared__ char sm[];
    const int tid = threadIdx.x, lane = tid & 31, warp = tid >> 5;
    const long long bz = blockIdx.z;
    const int row0 = blockIdx.y * 128, col0 = blockIdx.x * 64;
    const __half* srcA = A + sA*bz + (long long)row0*K;
    const __half* srcB = B + sB*bz + (long long)col0*K;
    const uint32_t sb = smem_u32(sm);

    auto stage_load = [&](int c, int buf) {
        const int k0 = c * 64;
        const uint32_t db = sb + buf * STG1;
        #pragma unroll
        for (int i = 0; i < 4; ++i) {            // A: 1024 chunks
            int idx = tid + i * 256;
            int row = (idx >> 3) & 127;
            int ch  = idx & 7;
            const __half* s = srcA + (long long)row * K + k0 + ch * 8;
            uint32_t d = db + row * PITCH + ch * 16;
            asm volatile("cp.async.cg.shared.global [%0], [%1], 16;" :: "r"(d), "l"(s));
        }
        #pragma unroll
        for (int i = 0; i < 2; ++i) {            // B: 512 chunks
            int j   = tid + i * 256;
            int row = (j >> 3) & 63;
            int ch  = j & 7;
            const __half* s = srcB + (long long)row * K + k0 + ch * 8;
            uint32_t d = db + ATILE + row * PITCH + ch * 16;
            asm volatile("cp.async.cg.shared.global [%0], [%1], 16;" :: "r"(d), "l"(s));
        }
        asm volatile("cp.async.commit_group;" ::: "memory");
    };

    const int wr = (warp & 3) * 32;
    const int wc = (warp >> 2) * 32;
    float acc[2][4][4] = {};

    const int rA = lane & 15;
    const int byA = (lane >> 4) * 16;
    const int rB = (lane & 7) + ((lane >> 3) & 1) * 8;
    const int byB = ((lane >> 4) & 1) * 16;

    const int nch = K >> 6;
    stage_load(0, 0);
    for (int c = 0; c < nch; ++c) {
        const int buf = c & 1;
        asm volatile("cp.async.wait_group 0;" ::: "memory");
        __syncthreads();
        if (c + 1 < nch) stage_load(c + 1, buf ^ 1);
        const uint32_t base = sb + buf * STG1;
        #pragma unroll
        for (int ks = 0; ks < 4; ++ks) {
            const int kb = ks * 32;
            uint32_t ah[2][4], bh[2][4];
            #pragma unroll
            for (int mi = 0; mi < 2; ++mi)
                ldsm4(ah[mi], base + (wr + mi*16 + rA) * PITCH + byA + kb);
            #pragma unroll
            for (int ng = 0; ng < 2; ++ng)
                ldsm4(bh[ng], base + ATILE + (wc + ng*16 + rB) * PITCH + byB + kb);
            #pragma unroll
            for (int mi = 0; mi < 2; ++mi)
                #pragma unroll
                for (int nj = 0; nj < 4; ++nj)
                    mma_fp(acc[mi][nj], ah[mi], bh[nj>>1][nj&1], bh[nj>>1][(nj&1)+2]);
        }
    }

    const int rb = row0 + wr + (lane >> 2);
    const int cb = col0 + wc + (lane & 3) * 2;
    __half* st = (__half*)sm;   // EPI==5 staging: [64 cols][pitch 136 halves]
    if (EPI == 5) __syncthreads();   // all reads of last buffer done before reuse as staging
    #pragma unroll
    for (int mi = 0; mi < 2; ++mi)
        #pragma unroll
        for (int h = 0; h < 2; ++h) {
            const int r = rb + mi * 16 + h * 8;
            #pragma unroll
            for (int nj = 0; nj < 4; ++nj) {
                const int colg = cb + nj * 8;
                float v0 = acc[mi][nj][2*h], v1 = acc[mi][nj][2*h + 1];
                if (EPI == 5) {
                    const int lr = r - row0, lc = colg - col0;
                    st[lc * 136 + lr]       = __float2half(v0 + bias[colg]);
                    st[(lc + 1) * 136 + lr] = __float2half(v1 + bias[colg + 1]);
                } else {
                    const long long oi = sC * bz + (long long)r * N + colg;
                    if (EPI == 0) {
                        *(float2*)(Cf + oi) = make_float2(v0, v1);
                    } else if (EPI == 1) {
                        *(float2*)(Cf + oi) = make_float2(v0 + bias[colg], v1 + bias[colg+1]);
                    } else {
                        const float2 xb = *(const float2*)(X + oi);
                        *(float2*)(Cf + oi) = make_float2(2.0f*(v0 + bias[colg]   + xb.x),
                                                          2.0f*(v1 + bias[colg+1] + xb.y));
                    }
                }
            }
        }
    if (EPI == 5) {
        __syncthreads();
        const int b = row0 >> 11;               // 128-row tile lies in one batch
        const int s0 = row0 & 2047;
        #pragma unroll
        for (int i = 0; i < 4; ++i) {
            int ch = tid + i * 256;             // 1024 chunks of 8 halves
            int c = ch >> 4, off = (ch & 15) * 8;
            uint4 val = *(const uint4*)(st + c * 136 + off);
            *(uint4*)(Ct + ((long long)b * EMB + col0 + c) * SEQ + s0 + off) = val;
        }
    }
}

// ------------------------------ reductions -----------------------------------
__device__ __forceinline__ float brSum(float v, float* sh) {
    #pragma unroll
    for (int o = 16; o > 0; o >>= 1) v += __shfl_down_sync(0xffffffffu, v, o);
    int ln = threadIdx.x & 31, w = threadIdx.x >> 5;
    __syncthreads();
    if (ln == 0) sh[w] = v;
    __syncthreads();
    if (w == 0) {
        v = (ln < 8) ? sh[ln] : 0.0f;
        #pragma unroll
        for (int o = 4; o > 0; o >>= 1) v += __shfl_down_sync(0xffffffffu, v, o);
        if (ln == 0) sh[0] = v;
    }
    __syncthreads();
    return sh[0];
}
__device__ __forceinline__ float brMax(float v, float* sh) {
    #pragma unroll
    for (int o = 16; o > 0; o >>= 1) v = fmaxf(v, __shfl_down_sync(0xffffffffu, v, o));
    int ln = threadIdx.x & 31, w = threadIdx.x >> 5;
    __syncthreads();
    if (ln == 0) sh[w] = v;
    __syncthreads();
    if (w == 0) {
        v = (ln < 8) ? sh[ln] : -1e30f;
        #pragma unroll
        for (int o = 4; o > 0; o >>= 1) v = fmaxf(v, __shfl_down_sync(0xffffffffu, v, o));
        if (ln == 0) sh[0] = v;
    }
    __syncthreads();
    return sh[0];
}

// ------------------------------ LN (vectorized, optional fused matvecs) -------
__global__ void __launch_bounds__(256) ln_kernel(
    const float* __restrict__ x, const float* __restrict__ g,
    const float* __restrict__ b, bf16* __restrict__ oh, bf16* __restrict__ ol,
    __half* __restrict__ o16,
    const float* __restrict__ w1, const float* __restrict__ w2,
    float* __restrict__ oc1, float* __restrict__ oc2)
{
    __shared__ float sh[32];
    const long long row = blockIdx.x;
    const int tid = threadIdx.x;
    const float4 t = ((const float4*)(x + row*EMB))[tid];
    float s  = t.x + t.y + t.z + t.w;
    float s2 = t.x*t.x + t.y*t.y + t.z*t.z + t.w*t.w;
    s  = brSum(s,  sh);
    s2 = brSum(s2, sh);
    const float mu  = s * (1.0f/EMB);
    const float inv = rsqrtf(s2*(1.0f/EMB) - mu*mu + 1e-5f);
    const float4 gv = ((const float4*)g)[tid];
    const float4 bv = ((const float4*)b)[tid];
    float y0 = (t.x - mu)*inv*gv.x + bv.x;
    float y1 = (t.y - mu)*inv*gv.y + bv.y;
    float y2 = (t.z - mu)*inv*gv.z + bv.z;
    float y3 = (t.w - mu)*inv*gv.w + bv.w;
    const long long o = row*EMB + tid*4;
    if (oh) {
        bf16 h0 = __float2bfloat16(y0), h1 = __float2bfloat16(y1);
        bf16 h2 = __float2bfloat16(y2), h3 = __float2bfloat16(y3);
        *(__nv_bfloat162*)(oh + o)     = __nv_bfloat162(h0, h1);
        *(__nv_bfloat162*)(oh + o + 2) = __nv_bfloat162(h2, h3);
        *(__nv_bfloat162*)(ol + o) = __nv_bfloat162(
            __float2bfloat16(y0 - __bfloat162float(h0)),
            __float2bfloat16(y1 - __bfloat162float(h1)));
        *(__nv_bfloat162*)(ol + o + 2) = __nv_bfloat162(
            __float2bfloat16(y2 - __bfloat162float(h2)),
            __float2bfloat16(y3 - __bfloat162float(h3)));
    }
    if (o16) {
        *(__half2*)(o16 + o)     = __half2(__float2half(y0), __float2half(y1));
        *(__half2*)(o16 + o + 2) = __half2(__float2half(y2), __float2half(y3));
    }
    if (oc1) {
        const float4 w1v = ((const float4*)w1)[tid];
        const float4 w2v = ((const float4*)w2)[tid];
        float t1 = y0*w1v.x + y1*w1v.y + y2*w1v.z + y3*w1v.w;
        float t2 = y0*w2v.x + y1*w2v.y + y2*w2v.z + y3*w2v.w;
        t1 = brSum(t1, sh);
        t2 = brSum(t2, sh);
        if (tid == 0) { oc1[row] = t1; oc2[row] = t2; }
    }
}

// ------------------------------ softmax (vectorized, fp16 out) ---------------
__global__ void __launch_bounds__(256) softmax_kernel(
    const float* __restrict__ S, __half* __restrict__ o16)
{
    __shared__ float sh[32];
    const long long row = blockIdx.x;
    const float4* p4 = (const float4*)(S + row * (long long)SEQ);
    const int tid = threadIdx.x;
    float4 a = p4[tid], b = p4[tid + 256];
    float vals[8] = {a.x, a.y, a.z, a.w, b.x, b.y, b.z, b.w};
    float m = -1e30f;
    #pragma unroll
    for (int i = 0; i < 8; i++) m = fmaxf(m, vals[i]);
    m = brMax(m, sh);
    float s = 0.f;
    #pragma unroll
    for (int i = 0; i < 8; i++) { vals[i] = __expf(vals[i] - m); s += vals[i]; }
    s = brSum(s, sh);
    const float inv = 1.0f/s;
    __half* po = o16 + row*SEQ;
    *(__half2*)(po + tid*4)        = __half2(__float2half(vals[0]*inv), __float2half(vals[1]*inv));
    *(__half2*)(po + tid*4 + 2)    = __half2(__float2half(vals[2]*inv), __float2half(vals[3]*inv));
    *(__half2*)(po + 1024 + tid*4)     = __half2(__float2half(vals[4]*inv), __float2half(vals[5]*inv));
    *(__half2*)(po + 1024 + tid*4 + 2) = __half2(__float2half(vals[6]*inv), __float2half(vals[7]*inv));
}

// --------- merged: fp32 -> bf16 hi/lo split for Wq and Wk in one launch ------
__global__ void __launch_bounds__(256) conv_split2(
    const float* __restrict__ inA, bf16* __restrict__ ohA, bf16* __restrict__ olA,
    const float* __restrict__ inB, bf16* __restrict__ ohB, bf16* __restrict__ olB)
{
    const bool second = blockIdx.x >= 1024;
    const float* in = second ? inB : inA;
    bf16* oh = second ? ohB : ohA;
    bf16* ol = second ? olB : olA;
    const long long i = (long long)(blockIdx.x & 1023) * 1024 + threadIdx.x * 4;
    const float4 t = *(const float4*)(in + i);
    float v[4] = {t.x, t.y, t.z, t.w};
    #pragma unroll
    for (int j = 0; j < 4; ++j) {
        bf16 h = __float2bfloat16(v[j]);
        oh[i + j] = h;
        ol[i + j] = __float2bfloat16(v[j] - __bfloat162float(h));
    }
}

// ------- merged: transpose fp32 [1024,1024] -> fp16 for Wv and Wfc -----------
__global__ void __launch_bounds__(256) tr_half2(
    const float* __restrict__ inA, __half* __restrict__ outA,
    const float* __restrict__ inB, __half* __restrict__ outB)
{
    __shared__ float t[32][33];
    const bool second = blockIdx.z >= 1;
    const float* in = second ? inB : inA;
    __half* out = second ? outB : outA;
    const int C = 1024, R = 1024;
    const int c0 = blockIdx.x*32, r0 = blockIdx.y*32;
    const int tx = threadIdx.x & 31, ty = threadIdx.x >> 5;
    #pragma unroll
    for (int i = 0; i < 4; i++)
        t[ty + i*8][tx] = in[(long long)(r0 + ty + i*8)*C + c0 + tx];
    __syncthreads();
    #pragma unroll
    for (int i = 0; i < 4; i++)
        out[(long long)(c0 + ty + i*8)*R + r0 + tx] = __float2half(t[tx][ty + i*8]);
}

// ------- merged bias prep: w1 = Wq@bk, w2 = Wk@bq, c3 = bq.bk ----------------
__global__ void __launch_bounds__(256) bias_prep(
    const float* __restrict__ Wq, const float* __restrict__ Wk,
    const float* __restrict__ bq, const float* __restrict__ bk,
    float* __restrict__ w1, float* __restrict__ w2, float* __restrict__ c3)
{
    __shared__ float sh[32];
    const int tid = threadIdx.x;
    const int bid = blockIdx.x;          // 0..2048
    const float *va, *vb;
    float* out;
    if (bid < 1024)      { va = Wq + (long long)bid * 1024;            vb = bk; out = w1 + bid; }
    else if (bid < 2048) { va = Wk + (long long)(bid - 1024) * 1024;   vb = bq; out = w2 + (bid - 1024); }
    else                 { va = bq;                                    vb = bk; out = c3; }
    float s = 0.f;
    #pragma unroll
    for (int i = 0; i < 4; i++) {
        int c = tid + i*256;
        s += va[c] * vb[c];
    }
    s = brSum(s, sh);
    if (tid == 0) *out = s;
}

// ------------------------------ launcher -------------------------------------
extern "C" void kernel_launch(void* const* d_in, const int* in_sizes, int n_in,
                              void* d_out, int out_size)
{
    const float* x   = (const float*)d_in[0];
    const float* Wq  = (const float*)d_in[1];
    const float* bq  = (const float*)d_in[2];
    const float* Wk  = (const float*)d_in[3];
    const float* bk  = (const float*)d_in[4];
    const float* Wv  = (const float*)d_in[5];
    const float* bv  = (const float*)d_in[6];
    const float* Wfc = (const float*)d_in[7];
    const float* bfc = (const float*)d_in[8];
    const float* g1  = (const float*)d_in[9];
    const float* b1  = (const float*)d_in[10];
    const float* g2  = (const float*)d_in[11];
    const float* b2  = (const float*)d_in[12];
    float* y = (float*)d_out;

    bf16 *wqsh,*wqsl,*wksh,*wksl,*mth,*mtl,*hh,*hl,*gh,*gl;
    __half *wvt,*wft,*h16,*vt16,*p16;
    float *s,*o,*zero,*w1,*w2,*c1,*c2,*c3;
    cudaGetSymbolAddress((void**)&wqsh, g_wqsh); cudaGetSymbolAddress((void**)&wqsl, g_wqsl);
    cudaGetSymbolAddress((void**)&wksh, g_wksh); cudaGetSymbolAddress((void**)&wksl, g_wksl);
    cudaGetSymbolAddress((void**)&mth, g_mth);   cudaGetSymbolAddress((void**)&mtl, g_mtl);
    cudaGetSymbolAddress((void**)&wvt, g_wvt);   cudaGetSymbolAddress((void**)&wft, g_wft);
    cudaGetSymbolAddress((void**)&hh, g_hh);     cudaGetSymbolAddress((void**)&hl, g_hl);
    cudaGetSymbolAddress((void**)&h16, g_h16);
    cudaGetSymbolAddress((void**)&gh, g_gh);     cudaGetSymbolAddress((void**)&gl, g_gl);
    cudaGetSymbolAddress((void**)&vt16, g_vt16);
    cudaGetSymbolAddress((void**)&p16, g_p16);
    cudaGetSymbolAddress((void**)&s, g_s);
    cudaGetSymbolAddress((void**)&o, g_o);
    cudaGetSymbolAddress((void**)&zero, g_zero);
    cudaGetSymbolAddress((void**)&w1, g_w1);     cudaGetSymbolAddress((void**)&w2, g_w2);
    cudaGetSymbolAddress((void**)&c1, g_c1);     cudaGetSymbolAddress((void**)&c2, g_c2);
    cudaGetSymbolAddress((void**)&c3, g_c3);

    cudaFuncSetAttribute(mm_hmma<2>, cudaFuncAttributeMaxDynamicSharedMemorySize, SMB3);
    cudaFuncSetAttribute(mm_hmma<4>, cudaFuncAttributeMaxDynamicSharedMemorySize, SMB3);
    cudaFuncSetAttribute(mm_fp16<0>, cudaFuncAttributeMaxDynamicSharedMemorySize, SMB1);
    cudaFuncSetAttribute(mm_fp16<3>, cudaFuncAttributeMaxDynamicSharedMemorySize, SMB1);
    cudaFuncSetAttribute(mm_fp16<5>, cudaFuncAttributeMaxDynamicSharedMemorySize, SMB1);

    const long long strQKV = (long long)SEQ*EMB;
    const long long strS   = (long long)SEQ*SEQ;

    // weight prep (merged launches)
    conv_split2<<<2048, 256>>>(Wq, wqsh, wqsl, Wk, wksh, wksl);
    tr_half2<<<dim3(32,32,2), 256>>>(Wv, wvt, Wfc, wft);
    bias_prep<<<2049, 256>>>(Wq, Wk, bq, bk, w1, w2, c3);
    // M^T = Wk @ Wq^T, split  (M = Wq @ Wk^T)
    mm_hmma<2><<<dim3(16,8,1), 256, SMB3>>>(wksh, wksl, wqsh, wqsl, zero,
                                            nullptr, nullptr, nullptr,
                                            nullptr, mth, mtl, EMB, EMB, 0, 0, 0);
    // LN1 -> bf16 split + fp16, fused c1/c2
    ln_kernel<<<MTOT, 256>>>(x, g1, b1, hh, hl, h16, w1, w2, c1, c2);
    // g = h @ M  (B operand = M^T), split out
    mm_hmma<2><<<dim3(16,128,1), 256, SMB3>>>(hh, hl, mth, mtl, zero,
                                              nullptr, nullptr, nullptr,
                                              nullptr, gh, gl, EMB, EMB, 0, 0, 0);
    // v-proj: fp16, fused transpose -> vt16 [B][EMB][SEQ]
    mm_fp16<5><<<dim3(16,128,1), 256, SMB1>>>(h16, wvt, bv, nullptr, nullptr, vt16,
                                              EMB, EMB, 0, 0, 0);
    // scores = g @ h^T + c1[row] + c2[col] + c3   (batched)
    mm_hmma<4><<<dim3(32,16,BATCH), 256, SMB3>>>(gh, gl, hh, hl, nullptr,
                                                 c1, c2, c3,
                                                 s, nullptr, nullptr, SEQ, EMB,
                                                 strQKV, strQKV, strS);
    // softmax -> fp16 probs
    softmax_kernel<<<MTOT, 256>>>(s, p16);
    // o = probs @ v: fp16 (batched), B operand = vt16
    mm_fp16<0><<<dim3(16,16,BATCH), 256, SMB1>>>(p16, vt16, nullptr, nullptr, o, nullptr,
                                                 EMB, SEQ, strS, strQKV, strQKV);
    // LN2 -> fp16 only
    ln_kernel<<<MTOT, 256>>>(o, g2, b2, nullptr, nullptr, h16,
                             nullptr, nullptr, nullptr, nullptr);
    // y = 2*(h2 @ Wfc + bfc + x): fp16
    mm_fp16<3><<<dim3(16,128,1), 256, SMB1>>>(h16, wft, bfc, x, y, nullptr,
                                              EMB, EMB, 0, 0, 0);
}